// round 1
// baseline (speedup 1.0000x reference)
#include <cuda_runtime.h>

#define HIDDEN   64
#define THREE_H  192
#define MB       2
#define NTHREADS (MB * THREE_H)

// ---------- packed f32x2 helpers (Blackwell FFMA2 path, PTX-only) ----------
__device__ __forceinline__ unsigned long long ffma2(unsigned long long a,
                                                    unsigned long long b,
                                                    unsigned long long c) {
    unsigned long long d;
    asm("fma.rn.f32x2 %0, %1, %2, %3;" : "=l"(d) : "l"(a), "l"(b), "l"(c));
    return d;
}
__device__ __forceinline__ unsigned long long fadd2(unsigned long long a,
                                                    unsigned long long b) {
    unsigned long long d;
    asm("add.rn.f32x2 %0, %1, %2;" : "=l"(d) : "l"(a), "l"(b));
    return d;
}
__device__ __forceinline__ unsigned long long pack2(float lo, float hi) {
    unsigned long long r;
    asm("mov.b64 %0, {%1, %2};" : "=l"(r) : "f"(lo), "f"(hi));
    return r;
}
__device__ __forceinline__ float2 unpack2(unsigned long long v) {
    float2 r;
    asm("mov.b64 {%0, %1}, %2;" : "=f"(r.x), "=f"(r.y) : "l"(v));
    return r;
}

// ---------- fast transcendentals (MUFU.EX2 / MUFU.RCP) ----------
__device__ __forceinline__ float fast_rcp(float x) {
    float r;
    asm("rcp.approx.f32 %0, %1;" : "=f"(r) : "f"(x));
    return r;
}
__device__ __forceinline__ float fast_exp(float x) {
    // exp(x) = 2^(x * log2(e))
    float r;
    asm("ex2.approx.f32 %0, %1;" : "=f"(r) : "f"(x * 1.4426950408889634f));
    return r;
}
__device__ __forceinline__ float fast_sigmoid(float a) {
    a = fminf(fmaxf(a, -30.0f), 30.0f);
    float e = fast_exp(-a);
    return fast_rcp(1.0f + e);
}
__device__ __forceinline__ float fast_tanh(float a) {
    a = fminf(fmaxf(a, -15.0f), 15.0f);
    float e = fast_exp(-2.0f * a);
    return (1.0f - e) * fast_rcp(1.0f + e);
}

// named barrier over one 192-thread batch group (ids 1 and 2; 0 left alone)
__device__ __forceinline__ void grpbar(int m) {
    asm volatile("bar.sync %0, %1;" :: "r"(m + 1), "r"(THREE_H) : "memory");
}

__global__ void __launch_bounds__(NTHREADS, 1)
gru_scan_kernel(const float* __restrict__ x,
                const float* __restrict__ W_ih,
                const float* __restrict__ W_hh,
                const float* __restrict__ b_ih,
                const float* __restrict__ b_hh,
                const float* __restrict__ W_fc,
                const float* __restrict__ b_fc,
                float* __restrict__ out,
                int Btotal, int T)
{
    __shared__ __align__(16) float h_sh[MB][HIDDEN];  // current hidden state
    __shared__ float z_sh[MB][HIDDEN];                // sigmoid(z) per step
    __shared__ float n_sh[MB][HIDDEN];                // dot_n + b_hh_n per step
    __shared__ float red_sh[MB][2];                   // fc reduction partials

    const int tid   = threadIdx.x;
    const int m     = tid / THREE_H;   // batch slot within CTA (0..MB-1)
    const int g     = tid % THREE_H;   // gate index 0..191
    const int gtype = g / HIDDEN;      // 0=r, 1=z, 2=n  (torch gate order)
    const int j     = g % HIDDEN;      // hidden unit
    const int b     = blockIdx.x * MB + m;
    const bool valid_b = (b < Btotal);

    // ---- load this gate's W_hh row into registers as 32 packed f32x2 ----
    unsigned long long w[32];
    {
        const float4* row = reinterpret_cast<const float4*>(W_hh + g * HIDDEN);
        #pragma unroll
        for (int i = 0; i < 16; i++) {
            float4 v = row[i];
            w[2 * i]     = pack2(v.x, v.y);
            w[2 * i + 1] = pack2(v.z, v.w);
        }
    }
    const float wih  = W_ih[g];
    const float bias = b_ih[g] + b_hh[g];   // merged bias for r,z sigmoid arg
    const float bhh_g = b_hh[g];            // kept separate for n gate
    // combine-thread (gtype==0) extra constants for the n gate and fc
    const float wih_n = W_ih[2 * HIDDEN + j];
    const float bih_n = b_ih[2 * HIDDEN + j];
    const float wfc   = W_fc[j];
    const float bfc   = __ldg(b_fc);

    // ---- init h = 0 ----
    if (gtype == 0) h_sh[m][j] = 0.0f;
    grpbar(m);

    const float* xb = x + (size_t)(valid_b ? b : 0) * T;
    float xv = __ldg(xb);   // x[b, 0]

    for (int t = 0; t < T; t++) {
        // prefetch next x (broadcast LDG, latency hidden behind the dot)
        int tn = t + 1 < T ? t + 1 : T - 1;
        float xnext = __ldg(xb + tn);

        // ---- gh[g] = sum_k W_hh[g,k] * h[k]  (FFMA2, 4 independent chains) ----
        const ulonglong2* h2 = reinterpret_cast<const ulonglong2*>(h_sh[m]);
        unsigned long long a0 = 0ull, a1 = 0ull, a2 = 0ull, a3 = 0ull;
        #pragma unroll
        for (int i = 0; i < 8; i++) {
            ulonglong2 hv0 = h2[2 * i];
            ulonglong2 hv1 = h2[2 * i + 1];
            a0 = ffma2(w[4 * i],     hv0.x, a0);
            a1 = ffma2(w[4 * i + 1], hv0.y, a1);
            a2 = ffma2(w[4 * i + 2], hv1.x, a2);
            a3 = ffma2(w[4 * i + 3], hv1.y, a3);
        }
        unsigned long long s = fadd2(fadd2(a0, a1), fadd2(a2, a3));
        float2 sp = unpack2(s);
        float dot = sp.x + sp.y;

        float rval = 0.0f;
        if (gtype == 1) {
            z_sh[m][j] = fast_sigmoid(fmaf(xv, wih, bias) + dot);
        } else if (gtype == 2) {
            n_sh[m][j] = dot + bhh_g;
        } else {
            rval = fast_sigmoid(fmaf(xv, wih, bias) + dot);
        }

        grpbar(m);   // publish z_sh / n_sh; all dot-phase h reads done

        if (gtype == 0) {
            float ndot = n_sh[m][j];
            float zval = z_sh[m][j];
            float hold = h_sh[m][j];
            float a    = fmaf(xv, wih_n, bih_n) + rval * ndot;
            float nval = fast_tanh(a);
            h_sh[m][j] = nval + zval * (hold - nval);   // (1-z)*n + z*h
        }

        grpbar(m);   // h_new visible before next step's dot reads
        xv = xnext;
    }

    // ---- out[b] = h . W_fc + b_fc ----
    if (gtype == 0) {
        float v = h_sh[m][j] * wfc;
        #pragma unroll
        for (int o = 16; o > 0; o >>= 1)
            v += __shfl_xor_sync(0xffffffffu, v, o);
        if ((j & 31) == 0) red_sh[m][j >> 5] = v;
    }
    grpbar(m);
    if (g == 0 && valid_b) {
        out[b] = red_sh[m][0] + red_sh[m][1] + bfc;
    }
}

extern "C" void kernel_launch(void* const* d_in, const int* in_sizes, int n_in,
                              void* d_out, int out_size)
{
    const float* x    = (const float*)d_in[0];
    const float* W_ih = (const float*)d_in[1];
    const float* W_hh = (const float*)d_in[2];
    const float* b_ih = (const float*)d_in[3];
    const float* b_hh = (const float*)d_in[4];
    const float* W_fc = (const float*)d_in[5];
    const float* b_fc = (const float*)d_in[6];

    int B = out_size;                 // 256
    int T = in_sizes[0] / B;          // 3000
    int grid = (B + MB - 1) / MB;     // 128 CTAs

    gru_scan_kernel<<<grid, NTHREADS>>>(x, W_ih, W_hh, b_ih, b_hh, W_fc, b_fc,
                                        (float*)d_out, B, T);
}

// round 2
// speedup vs baseline: 1.0682x; 1.0682x over previous
#include <cuda_runtime.h>

#define HIDDEN   64
#define THREE_H  192
#define GROUP    384               // threads per batch element (2-way k split)
#define MB       2
#define NTHREADS (MB * GROUP)      // 768

// ---------- packed f32x2 helpers (Blackwell FFMA2 path, PTX-only) ----------
__device__ __forceinline__ unsigned long long ffma2(unsigned long long a,
                                                    unsigned long long b,
                                                    unsigned long long c) {
    unsigned long long d;
    asm("fma.rn.f32x2 %0, %1, %2, %3;" : "=l"(d) : "l"(a), "l"(b), "l"(c));
    return d;
}
__device__ __forceinline__ unsigned long long fadd2(unsigned long long a,
                                                    unsigned long long b) {
    unsigned long long d;
    asm("add.rn.f32x2 %0, %1, %2;" : "=l"(d) : "l"(a), "l"(b));
    return d;
}
__device__ __forceinline__ unsigned long long pack2(float lo, float hi) {
    unsigned long long r;
    asm("mov.b64 %0, {%1, %2};" : "=l"(r) : "f"(lo), "f"(hi));
    return r;
}
__device__ __forceinline__ float2 unpack2(unsigned long long v) {
    float2 r;
    asm("mov.b64 {%0, %1}, %2;" : "=f"(r.x), "=f"(r.y) : "l"(v));
    return r;
}

// ---------- fast transcendentals (MUFU.EX2 / MUFU.RCP) ----------
__device__ __forceinline__ float fast_rcp(float x) {
    float r; asm("rcp.approx.f32 %0, %1;" : "=f"(r) : "f"(x)); return r;
}
__device__ __forceinline__ float fast_exp(float x) {
    float r; asm("ex2.approx.f32 %0, %1;" : "=f"(r) : "f"(x * 1.4426950408889634f));
    return r;
}
__device__ __forceinline__ float fast_sigmoid(float a) {
    a = fminf(fmaxf(a, -30.0f), 30.0f);
    return fast_rcp(1.0f + fast_exp(-a));
}
__device__ __forceinline__ float fast_tanh(float a) {
    a = fminf(fmaxf(a, -15.0f), 15.0f);
    float e = fast_exp(-2.0f * a);
    return (1.0f - e) * fast_rcp(1.0f + e);
}

// named barrier over one 384-thread batch group (ids 1 and 2)
__device__ __forceinline__ void grpbar(int m) {
    asm volatile("bar.sync %0, %1;" :: "r"(m + 1), "r"(GROUP) : "memory");
}

__global__ void __launch_bounds__(NTHREADS, 1)
gru_scan_kernel(const float* __restrict__ x,
                const float* __restrict__ W_ih,
                const float* __restrict__ W_hh,
                const float* __restrict__ b_ih,
                const float* __restrict__ b_hh,
                const float* __restrict__ W_fc,
                const float* __restrict__ b_fc,
                float* __restrict__ out,
                int Btotal, int T)
{
    __shared__ __align__(16) float h_sh[MB][HIDDEN];          // current hidden state
    __shared__ unsigned long long psum[MB][3][2][HIDDEN];     // raw f32x2 dot partials
    __shared__ float red_sh[MB][2];                           // fc reduction partials

    const int tid   = threadIdx.x;
    const int m     = tid / GROUP;       // batch slot in CTA
    const int u     = tid % GROUP;
    const int half  = u / THREE_H;       // k-split half: 0 -> k[0:32), 1 -> k[32:64)
    const int g     = u % THREE_H;       // gate row 0..191
    const int gtype = g / HIDDEN;        // 0=r, 1=z, 2=n (torch order)
    const int j     = g % HIDDEN;        // hidden unit
    const int b     = blockIdx.x * MB + m;

    // ---- this thread's half-row of W_hh as 16 packed f32x2 (32 regs) ----
    unsigned long long w[16];
    {
        const float4* row = reinterpret_cast<const float4*>(W_hh + g * HIDDEN + half * 32);
        #pragma unroll
        for (int i = 0; i < 8; i++) {
            float4 v = row[i];
            w[2 * i]     = pack2(v.x, v.y);
            w[2 * i + 1] = pack2(v.z, v.w);
        }
    }

    // combine warps: gtype==0, half==m  -> batch0 on warps 0,1 (SMSP 0/1),
    // batch1 on warps 18,19 (SMSP 2/3). Warp-uniform predicate.
    const bool is_comb = (gtype == 0) && (half == m);

    // combine-only constants
    float wr = 0.f, wz = 0.f, wn = 0.f, brz_r = 0.f, brz_z = 0.f;
    float bn_i = 0.f, bn_h = 0.f, wfc = 0.f, bfc = 0.f;
    float h_old = 0.0f, xv = 0.0f;
    const float* xb = x + (size_t)b * T;
    if (is_comb) {
        wr    = W_ih[j];
        wz    = W_ih[HIDDEN + j];
        wn    = W_ih[2 * HIDDEN + j];
        brz_r = b_ih[j]          + b_hh[j];
        brz_z = b_ih[HIDDEN + j] + b_hh[HIDDEN + j];
        bn_i  = b_ih[2 * HIDDEN + j];
        bn_h  = b_hh[2 * HIDDEN + j];
        wfc   = W_fc[j];
        bfc   = __ldg(b_fc);
        xv    = __ldg(xb);           // x[b, 0]
        h_sh[m][j] = 0.0f;
    }
    grpbar(m);

    const ulonglong2* h2 = reinterpret_cast<const ulonglong2*>(h_sh[m] + half * 32);
    unsigned long long* myslot = &psum[m][gtype][half][j];

    for (int t = 0; t < T; t++) {
        // prefetch next x (combine threads only; L1-resident most steps)
        float xnext = 0.0f;
        if (is_comb) {
            int tn = (t + 1 < T) ? t + 1 : T - 1;
            xnext = __ldg(xb + tn);
        }

        // ---- half-dot: 8 LDS.128 + 16 FFMA2, 4 independent chains ----
        unsigned long long a0 = 0ull, a1 = 0ull, a2 = 0ull, a3 = 0ull;
        #pragma unroll
        for (int i = 0; i < 4; i++) {
            ulonglong2 hv0 = h2[2 * i];
            ulonglong2 hv1 = h2[2 * i + 1];
            a0 = ffma2(w[4 * i],     hv0.x, a0);
            a1 = ffma2(w[4 * i + 1], hv0.y, a1);
            a2 = ffma2(w[4 * i + 2], hv1.x, a2);
            a3 = ffma2(w[4 * i + 3], hv1.y, a3);
        }
        *myslot = fadd2(fadd2(a0, a1), fadd2(a2, a3));   // one STS.64, still packed

        grpbar(m);   // partials published

        if (is_comb) {
            unsigned long long pr = fadd2(psum[m][0][0][j], psum[m][0][1][j]);
            unsigned long long pz = fadd2(psum[m][1][0][j], psum[m][1][1][j]);
            unsigned long long pn = fadd2(psum[m][2][0][j], psum[m][2][1][j]);
            float2 r2 = unpack2(pr), z2 = unpack2(pz), n2 = unpack2(pn);
            float dr = r2.x + r2.y;
            float dz = z2.x + z2.y;
            float dn = n2.x + n2.y;

            float r    = fast_sigmoid(fmaf(xv, wr, brz_r) + dr);
            float z    = fast_sigmoid(fmaf(xv, wz, brz_z) + dz);
            float nval = fast_tanh(fmaf(xv, wn, bn_i) + r * (dn + bn_h));
            h_old = nval + z * (h_old - nval);     // (1-z)*n + z*h
            h_sh[m][j] = h_old;
            xv = xnext;
        }

        grpbar(m);   // h_new visible for next step's dots
    }

    // ---- out[b] = h . W_fc + b_fc (combine threads hold h in regs) ----
    if (is_comb) {
        float v = h_old * wfc;
        #pragma unroll
        for (int o = 16; o > 0; o >>= 1)
            v += __shfl_xor_sync(0xffffffffu, v, o);
        if ((j & 31) == 0) red_sh[m][j >> 5] = v;
    }
    grpbar(m);
    if (is_comb && j == 0 && b < Btotal) {
        out[b] = red_sh[m][0] + red_sh[m][1] + bfc;
    }
}

extern "C" void kernel_launch(void* const* d_in, const int* in_sizes, int n_in,
                              void* d_out, int out_size)
{
    const float* x    = (const float*)d_in[0];
    const float* W_ih = (const float*)d_in[1];
    const float* W_hh = (const float*)d_in[2];
    const float* b_ih = (const float*)d_in[3];
    const float* b_hh = (const float*)d_in[4];
    const float* W_fc = (const float*)d_in[5];
    const float* b_fc = (const float*)d_in[6];

    int B = out_size;                 // 256
    int T = in_sizes[0] / B;          // 3000
    int grid = (B + MB - 1) / MB;     // 128 CTAs -> 1 per SM

    gru_scan_kernel<<<grid, NTHREADS>>>(x, W_ih, W_hh, b_ih, b_hh, W_fc, b_fc,
                                        (float*)d_out, B, T);
}

// round 3
// speedup vs baseline: 1.1111x; 1.0402x over previous
#include <cuda_runtime.h>

#define HIDDEN   64
#define THREE_H  192
#define GROUP    192               // threads per batch element: one full W_hh row each
#define MB       2
#define NTHREADS (MB * GROUP)      // 384

// ---------- packed f32x2 helpers (Blackwell FFMA2 path, PTX-only) ----------
__device__ __forceinline__ unsigned long long ffma2(unsigned long long a,
                                                    unsigned long long b,
                                                    unsigned long long c) {
    unsigned long long d;
    asm("fma.rn.f32x2 %0, %1, %2, %3;" : "=l"(d) : "l"(a), "l"(b), "l"(c));
    return d;
}
__device__ __forceinline__ unsigned long long fadd2(unsigned long long a,
                                                    unsigned long long b) {
    unsigned long long d;
    asm("add.rn.f32x2 %0, %1, %2;" : "=l"(d) : "l"(a), "l"(b));
    return d;
}
__device__ __forceinline__ unsigned long long pack2(float lo, float hi) {
    unsigned long long r;
    asm("mov.b64 %0, {%1, %2};" : "=l"(r) : "f"(lo), "f"(hi));
    return r;
}
__device__ __forceinline__ float2 unpack2(unsigned long long v) {
    float2 r;
    asm("mov.b64 {%0, %1}, %2;" : "=f"(r.x), "=f"(r.y) : "l"(v));
    return r;
}

// ---------- nonlinearity primitives ----------
__device__ __forceinline__ float tanh_approx(float x) {     // 1 MUFU
    float r; asm("tanh.approx.f32 %0, %1;" : "=f"(r) : "f"(x)); return r;
}
__device__ __forceinline__ float fast_rcp(float x) {
    float r; asm("rcp.approx.f32 %0, %1;" : "=f"(r) : "f"(x)); return r;
}
__device__ __forceinline__ float fast_ex2(float x) {
    float r; asm("ex2.approx.f32 %0, %1;" : "=f"(r) : "f"(x)); return r;
}
// accurate tanh via exp(-2a): used for the n gate (direct h contributor)
__device__ __forceinline__ float tanh_accurate(float a) {
    a = fmaxf(a, -15.0f);                       // avoid inf on the negative side
    float e = fast_ex2(a * -2.885390081777927f); // exp(-2a) = 2^(-2a*log2e)
    return (1.0f - e) * fast_rcp(1.0f + e);
}

// named barrier over one 192-thread batch group
__device__ __forceinline__ void bar_named(int id) {
    asm volatile("bar.sync %0, %1;" :: "r"(id), "r"(GROUP) : "memory");
}

__global__ void __launch_bounds__(NTHREADS, 1)
gru_scan_kernel(const float* __restrict__ x,
                const float* __restrict__ W_ih,
                const float* __restrict__ W_hh,
                const float* __restrict__ b_ih,
                const float* __restrict__ b_hh,
                const float* __restrict__ W_fc,
                const float* __restrict__ b_fc,
                float* __restrict__ out,
                int Btotal, int T)
{
    __shared__ __align__(16) float h_sh[MB][HIDDEN];   // hidden state (dot input)
    __shared__ float rz_sh[MB][2][HIDDEN];             // r-dot, z-dot scalars
    __shared__ float red_sh[MB][2];                    // fc partials

    const int tid   = threadIdx.x;
    const int m     = tid / GROUP;       // batch slot
    const int g     = tid % GROUP;       // gate row 0..191
    const int gtype = g / HIDDEN;        // 0=r, 1=z, 2=n (torch order)
    const int j     = g % HIDDEN;
    const int b     = blockIdx.x * MB + m;
    const bool is_n = (gtype == 2);      // n-threads do the combine (warps 4,5 / 10,11)

    // ---- full W_hh row in registers: 32 packed f32x2 ----
    unsigned long long w[32];
    {
        const float4* row = reinterpret_cast<const float4*>(W_hh + g * HIDDEN);
        #pragma unroll
        for (int i = 0; i < 16; i++) {
            float4 v = row[i];
            w[2 * i]     = pack2(v.x, v.y);
            w[2 * i + 1] = pack2(v.z, v.w);
        }
    }

    // combine-thread constants
    float wr = 0.f, wz = 0.f, wn = 0.f, br = 0.f, bz = 0.f;
    float bihn = 0.f, bhhn = 0.f, wfc = 0.f, bfc = 0.f;
    float h_old = 0.0f, xv = 0.0f;
    const float* xb = x + (size_t)((b < Btotal) ? b : 0) * T;
    if (is_n) {
        wr   = W_ih[j];
        wz   = W_ih[HIDDEN + j];
        wn   = W_ih[2 * HIDDEN + j];
        br   = b_ih[j]          + b_hh[j];
        bz   = b_ih[HIDDEN + j] + b_hh[HIDDEN + j];
        bihn = b_ih[2 * HIDDEN + j];
        bhhn = b_hh[2 * HIDDEN + j];
        wfc  = W_fc[j];
        bfc  = __ldg(b_fc);
        xv   = __ldg(xb);
        h_sh[m][j] = 0.0f;
    }
    bar_named(2 + 2 * m);   // h ready

    const ulonglong2* h2 = reinterpret_cast<const ulonglong2*>(h_sh[m]);

    for (int t = 0; t < T; t++) {
        // off-critical-path precompute (n-threads): next x + input-gate terms
        float xnext = 0.0f, irh = 0.0f, izh = 0.0f, i_n = 0.0f;
        if (is_n) {
            int tn = (t + 1 < T) ? t + 1 : T - 1;
            xnext = __ldg(xb + tn);
            irh = 0.5f * fmaf(xv, wr, br);   // pre-halved sigmoid args
            izh = 0.5f * fmaf(xv, wz, bz);
            i_n = fmaf(xv, wn, bihn);
        }

        // ---- full-row dot: 16 LDS.128 + 32 FFMA2, 8 independent chains ----
        unsigned long long acc[8];
        {
            ulonglong2 hv0 = h2[0], hv1 = h2[1], hv2 = h2[2], hv3 = h2[3];
            acc[0] = ffma2(w[0], hv0.x, 0ull);
            acc[1] = ffma2(w[1], hv0.y, 0ull);
            acc[2] = ffma2(w[2], hv1.x, 0ull);
            acc[3] = ffma2(w[3], hv1.y, 0ull);
            acc[4] = ffma2(w[4], hv2.x, 0ull);
            acc[5] = ffma2(w[5], hv2.y, 0ull);
            acc[6] = ffma2(w[6], hv3.x, 0ull);
            acc[7] = ffma2(w[7], hv3.y, 0ull);
        }
        #pragma unroll
        for (int kk = 1; kk < 4; kk++) {
            ulonglong2 hv0 = h2[4 * kk + 0], hv1 = h2[4 * kk + 1];
            ulonglong2 hv2 = h2[4 * kk + 2], hv3 = h2[4 * kk + 3];
            acc[0] = ffma2(w[8 * kk + 0], hv0.x, acc[0]);
            acc[1] = ffma2(w[8 * kk + 1], hv0.y, acc[1]);
            acc[2] = ffma2(w[8 * kk + 2], hv1.x, acc[2]);
            acc[3] = ffma2(w[8 * kk + 3], hv1.y, acc[3]);
            acc[4] = ffma2(w[8 * kk + 4], hv2.x, acc[4]);
            acc[5] = ffma2(w[8 * kk + 5], hv2.y, acc[5]);
            acc[6] = ffma2(w[8 * kk + 6], hv3.x, acc[6]);
            acc[7] = ffma2(w[8 * kk + 7], hv3.y, acc[7]);
        }
        unsigned long long s = fadd2(fadd2(fadd2(acc[0], acc[1]), fadd2(acc[2], acc[3])),
                                     fadd2(fadd2(acc[4], acc[5]), fadd2(acc[6], acc[7])));
        float2 sp = unpack2(s);
        float dot = sp.x + sp.y;

        float dnb = 0.0f;
        if (!is_n) {
            rz_sh[m][gtype][j] = dot;        // publish r/z dots
        } else {
            dnb = dot + bhhn;                // n-dot stays local
        }

        bar_named(1 + 2 * m);   // r/z dots visible to n-threads

        if (is_n) {
            float dr = rz_sh[m][0][j];
            float dz = rz_sh[m][1][j];
            // sigmoid(s) = 0.5*tanh(0.5 s) + 0.5   (tanh.approx, 1 MUFU)
            float r = fmaf(0.5f, tanh_approx(fmaf(0.5f, dr, irh)), 0.5f);
            float z = fmaf(0.5f, tanh_approx(fmaf(0.5f, dz, izh)), 0.5f);
            float nval = tanh_accurate(fmaf(r, dnb, i_n));   // accurate path
            h_old = nval + z * (h_old - nval);               // (1-z)*n + z*h
            h_sh[m][j] = h_old;
            xv = xnext;
        }

        bar_named(2 + 2 * m);   // h_new visible for next step
    }

    // ---- out[b] = h . W_fc + b_fc (h lives in n-threads' registers) ----
    if (is_n) {
        float v = h_old * wfc;
        #pragma unroll
        for (int o = 16; o > 0; o >>= 1)
            v += __shfl_xor_sync(0xffffffffu, v, o);
        if ((j & 31) == 0) red_sh[m][j >> 5] = v;
    }
    bar_named(1 + 2 * m);
    if (is_n && j == 0 && b < Btotal) {
        out[b] = red_sh[m][0] + red_sh[m][1] + bfc;
    }
}

extern "C" void kernel_launch(void* const* d_in, const int* in_sizes, int n_in,
                              void* d_out, int out_size)
{
    const float* x    = (const float*)d_in[0];
    const float* W_ih = (const float*)d_in[1];
    const float* W_hh = (const float*)d_in[2];
    const float* b_ih = (const float*)d_in[3];
    const float* b_hh = (const float*)d_in[4];
    const float* W_fc = (const float*)d_in[5];
    const float* b_fc = (const float*)d_in[6];

    int B = out_size;                 // 256
    int T = in_sizes[0] / B;          // 3000
    int grid = (B + MB - 1) / MB;     // 128 CTAs -> 1 per SM

    gru_scan_kernel<<<grid, NTHREADS>>>(x, W_ih, W_hh, b_ih, b_hh, W_fc, b_fc,
                                        (float*)d_out, B, T);
}